// round 11
// baseline (speedup 1.0000x reference)
#include <cuda_runtime.h>
#include <cstdint>

// ============================ problem constants ============================
constexpr int IMGC = 224;
constexpr int KTOT = IMGC * IMGC;     // 50176
constexpr int BQ   = 256;
constexpr int JN   = 25;
constexpr int TN   = 64;
constexpr int OUTN = 256;
constexpr int MIDJ = JN / 2;          // 12
constexpr int BOXC = 20;

constexpr int XG   = 37;              // x windows (grid.x)
constexpr int NO   = 8;               // n octants (grid.y), 32 n each
constexpr int NCOL = 32;
constexpr int EVS  = 32;              // int16 slots per (b,x): [count, ev...]
constexpr uint32_t SMEM_MAIN = 224 * NCOL * 4;   // 28672 B: A[224y][32n] swz

// ============================ scratch (device globals) =====================
__device__ __align__(256) unsigned long long g_bits[(size_t)IMGC * BQ * 4]; // 1.8MB
__device__ __align__(256) short g_ev[(size_t)IMGC * BQ * EVS];              // 3.7MB
__device__ __align__(256) float g_part[(size_t)XG * BQ * OUTN];             // 9.7MB
__device__ int g_px[BQ * JN];
__device__ int g_ylo[BQ * JN];
__device__ int g_yhi[BQ * JN];

// ============================ kernel 1: farthest-frame box params ==========
__global__ void prep_kernel(const float* __restrict__ sk) {
    int id = blockIdx.x * blockDim.x + threadIdx.x;
    if (id >= BQ * JN) return;
    int b = id / JN, j = id % JN;
    const float* base = sk + ((size_t)b * JN + j) * TN * 3;
    const float* midb = sk + ((size_t)b * JN + MIDJ) * TN * 3;

    float best = -1.0f;
    int   tb = 0;
    for (int t = 0; t < TN; t++) {
        float dx = base[t * 3 + 0] - midb[t * 3 + 0];
        float dy = base[t * 3 + 1] - midb[t * 3 + 1];
        float dz = base[t * 3 + 2] - midb[t * 3 + 2];
        float d2 = __fadd_rn(__fadd_rn(__fmul_rn(dx, dx), __fmul_rn(dy, dy)),
                             __fmul_rn(dz, dz));
        float d = __fsqrt_rn(d2);
        if (d > best) { best = d; tb = t; }   // first-max == argmax semantics
    }
    float x = base[tb * 3 + 0];
    float y = base[tb * 3 + 1];
    int px = (int)(__fmul_rn(x, 224.0f));     // truncation == astype(int32)
    int py = (int)(__fmul_rn(y, 224.0f));
    g_px[id]  = px;
    g_ylo[id] = (py < BOXC) ? 0 : py - BOXC;
    g_yhi[id] = (py > IMGC - BOXC) ? IMGC : py + BOXC;
}

// ============================ kernel 2: per-(b,x) y-bitmask =================
__global__ void bitmask_kernel() {
    const int b = blockIdx.x;
    const int x = threadIdx.x;

    __shared__ int spx[JN], slo[JN], shi[JN];
    if (x < JN) {
        spx[x] = g_px[b * JN + x];
        slo[x] = g_ylo[b * JN + x];
        shi[x] = g_yhi[b * JN + x];
    }
    __syncthreads();

    unsigned long long m[4] = {0ull, 0ull, 0ull, 0ull};
#pragma unroll
    for (int j = 0; j < JN; j++) {
        if (j == MIDJ) continue;
        int px = spx[j];
        if (x >= px - BOXC && x < px + BOXC) {
            int lo = slo[j], hi = shi[j];
#pragma unroll
            for (int w = 0; w < 4; w++) {
                int l = lo - w * 64;  if (l < 0)  l = 0;
                int h = hi - w * 64;  if (h > 64) h = 64;
                if (l < h) {
                    unsigned long long hiM = (h == 64) ? ~0ull : ((1ull << h) - 1ull);
                    unsigned long long loM = (1ull << l) - 1ull;
                    m[w] |= hiM & ~loM;
                }
            }
        }
    }
    unsigned long long* dst = g_bits + ((size_t)x * BQ + b) * 4;
    dst[0] = m[0]; dst[1] = m[1]; dst[2] = m[2]; dst[3] = m[3];
}

// ============================ kernel 2b: boundary diff events ==============
// For each (b,x): signed difference of transition sets of m_x and m_{x+1}.
// Event = int16: low byte y, high byte coef in {-2,-1,1,2}. Slot0 = count;
// count 255 = overflow sentinel (main falls back to dual mask walk).
__global__ void diff_kernel() {
    const int x = blockIdx.x;
    const int b = threadIdx.x;

    const unsigned long long* pa = g_bits + ((size_t)x * BQ + b) * 4;
    unsigned long long ma0 = pa[0], ma1 = pa[1], ma2 = pa[2], ma3 = pa[3];
    unsigned long long mb0 = 0, mb1 = 0, mb2 = 0, mb3 = 0;
    if (x + 1 < IMGC) {
        const unsigned long long* pb = g_bits + ((size_t)(x + 1) * BQ + b) * 4;
        mb0 = pb[0]; mb1 = pb[1]; mb2 = pb[2]; mb3 = pb[3];
    }
    unsigned long long DA[4], DB[4];
    DA[0] = ma0 ^ ((ma0 >> 1) | (ma1 << 63));
    DA[1] = ma1 ^ ((ma1 >> 1) | (ma2 << 63));
    DA[2] = ma2 ^ ((ma2 >> 1) | (ma3 << 63));
    DA[3] = ma3 ^ (ma3 >> 1);
    DB[0] = mb0 ^ ((mb0 >> 1) | (mb1 << 63));
    DB[1] = mb1 ^ ((mb1 >> 1) | (mb2 << 63));
    DB[2] = mb2 ^ ((mb2 >> 1) | (mb3 << 63));
    DB[3] = mb3 ^ (mb3 >> 1);

    int sA = (ma0 & 1ull) ? 1 : -1;
    int sB = (mb0 & 1ull) ? 1 : -1;

    short* out = g_ev + ((size_t)x * BQ + b) * EVS;
    int cnt = 0;
#pragma unroll
    for (int wd = 0; wd < 4; wd++) {
        unsigned long long da = DA[wd], db = DB[wd];
        unsigned long long o = da | db;
        while (o) {
            int p = __ffsll((long long)o) - 1;
            o &= o - 1;
            int c = 0;
            if ((da >> p) & 1ull) { c += sA; sA = -sA; }
            if ((db >> p) & 1ull) { c -= sB; sB = -sB; }
            if (c != 0) {
                if (cnt < EVS - 1)
                    out[1 + cnt] = (short)(((wd * 64 + p) & 0xFF) | (c << 8));
                cnt++;
            }
        }
    }
    out[0] = (cnt > EVS - 1) ? (short)255 : (short)cnt;
}

// ============================ main kernel helpers ===========================
// Walk transition mask of *mp_ against accumulated prefix A; mult = overall
// sign. Validated gather core from R10 (NCOL=32 rotate swizzle).
__device__ __forceinline__ void walk_mask(const unsigned long long* mp_,
                                          float mult, float4* acc,
                                          const float* sA_, int half) {
    const ulonglong2* mp = reinterpret_cast<const ulonglong2*>(mp_);
    ulonglong2 mA = __ldg(mp), mB = __ldg(mp + 1);
    unsigned long long d0 = mA.x ^ ((mA.x >> 1) | (mA.y << 63));
    unsigned long long d1 = mA.y ^ ((mA.y >> 1) | (mB.x << 63));
    unsigned long long d2 = mB.x ^ ((mB.x >> 1) | (mB.y << 63));
    unsigned long long d3 = mB.y ^ (mB.y >> 1);
    float sgn = (mA.x & 1ull) ? mult : -mult;

#pragma unroll
    for (int wd = 0; wd < 4; wd++) {
        unsigned long long d = (wd == 0) ? d0 : (wd == 1) ? d1
                             : (wd == 2) ? d2 : d3;
        while (d) {
            int p = __ffsll((long long)d) - 1;
            d &= d - 1;
            const int y = wd * 64 + p;
            const float4* row = reinterpret_cast<const float4*>(sA_) + y * 8;
#pragma unroll
            for (int r = 0; r < 4; r++) {
                float4 t = row[(half * 4 + r + y) & 7];
                acc[r].x = fmaf(sgn, t.x, acc[r].x);
                acc[r].y = fmaf(sgn, t.y, acc[r].y);
                acc[r].z = fmaf(sgn, t.z, acc[r].z);
                acc[r].w = fmaf(sgn, t.w, acc[r].w);
            }
            sgn = -sgn;
        }
    }
}

// ============================ kernel 3: A-accumulating scan + sparse gather =
// grid (37, 8) = 296 CTAs = 2/SM. Per x in window:
//  scan  : warp w scans cols 2w,2w+1 and A[y] += prefix (A = x-accumulated)
//  gather: thread (b = tid/2, half): internal x -> diff events (usually 0);
//          last x of window -> full walk of m_x (telescoped strip sums).
__global__ __launch_bounds__(512, 2)
void main_kernel(const float* __restrict__ W) {
    extern __shared__ float sA[];
    const int tid  = threadIdx.x;
    const int w    = tid >> 5;
    const int lane = tid & 31;
    const int xg   = blockIdx.x;
    const int n0   = blockIdx.y * NCOL;
    const int b    = tid >> 1;
    const int half = tid & 1;

    const int x0 = (xg * IMGC) / XG;
    const int x1 = ((xg + 1) * IMGC) / XG;

    // zero A
#pragma unroll
    for (int r = 0; r < 14; r++) sA[tid + r * 512] = 0.f;

    float4 acc[4];
#pragma unroll
    for (int r = 0; r < 4; r++) acc[r] = make_float4(0.f, 0.f, 0.f, 0.f);
    __syncthreads();

    for (int x = x0; x < x1; x++) {
        // ---- scan + A update: 2 cols per warp ----
#pragma unroll
        for (int c = 0; c < 2; c++) {
            const int n = w * 2 + c;
            const float* wp = W + (size_t)(n0 + n) * KTOT + x * IMGC + lane;
            float v[7];
#pragma unroll
            for (int s = 0; s < 7; s++) v[s] = __ldg(wp + s * 32);

            float carry = 0.f;
            const int g4 = n >> 2;
            const int nc = n & 3;
#pragma unroll
            for (int s = 0; s < 7; s++) {
                float val = v[s];
#pragma unroll
                for (int off = 1; off < 32; off <<= 1) {
                    float t = __shfl_up_sync(0xffffffffu, val, off);
                    if (lane >= off) val += t;
                }
                val += carry;
                const int y = s * 32 + lane;
                sA[y * 32 + (((g4 + y) & 7) << 2) + nc] += val;
                carry = __shfl_sync(0xffffffffu, val, 31);
            }
        }
        __syncthreads();

        // ---- gather ----
        if (x == x1 - 1) {
            walk_mask(g_bits + ((size_t)x * BQ + b) * 4, 1.f, acc, sA, half);
        } else {
            const short* ev = g_ev + ((size_t)x * BQ + b) * EVS;
            const int cnt = (int)__ldg(ev);
            if (cnt == 255) {
                walk_mask(g_bits + ((size_t)x * BQ + b) * 4,  1.f, acc, sA, half);
                walk_mask(g_bits + ((size_t)(x + 1) * BQ + b) * 4, -1.f, acc, sA, half);
            } else {
                for (int e = 0; e < cnt; e++) {
                    const int v = (int)__ldg(ev + 1 + e);
                    const int y = v & 0xFF;
                    const float fc = (float)(v >> 8);
                    const float4* row = reinterpret_cast<const float4*>(sA) + y * 8;
#pragma unroll
                    for (int r = 0; r < 4; r++) {
                        float4 t = row[(half * 4 + r + y) & 7];
                        acc[r].x = fmaf(fc, t.x, acc[r].x);
                        acc[r].y = fmaf(fc, t.y, acc[r].y);
                        acc[r].z = fmaf(fc, t.z, acc[r].z);
                        acc[r].w = fmaf(fc, t.w, acc[r].w);
                    }
                }
            }
        }
        __syncthreads();
    }

    // ---- write partials: acc[r] holds n = n0 + half*16 + 4r .. +3 ----
    float4* dst = reinterpret_cast<float4*>(
        g_part + ((size_t)xg * BQ + b) * OUTN + n0 + half * 16);
#pragma unroll
    for (int r = 0; r < 4; r++) dst[r] = acc[r];
}

// ============================ kernel 4: reduce + bias + rgb multiply ========
__global__ void final_kernel(const float* __restrict__ rgb,
                             const float* __restrict__ bias,
                             float* __restrict__ out) {
    const int b = blockIdx.x;
    const int o = threadIdx.x;
    float acc = 0.0f;
    const float* p = g_part + b * OUTN + o;
#pragma unroll
    for (int s = 0; s < XG; s++)
        acc += p[(size_t)s * (BQ * OUTN)];
    out[b * OUTN + o] = rgb[b * OUTN + o] * (acc + bias[o]);
}

// ============================ launch ========================================
extern "C" void kernel_launch(void* const* d_in, const int* in_sizes, int n_in,
                              void* d_out, int out_size) {
    const float* rgb = nullptr;
    const float* sk  = nullptr;
    const float* W   = nullptr;
    const float* bias = nullptr;
    for (int i = 0; i < n_in; i++) {
        switch (in_sizes[i]) {
            case BQ * OUTN:          rgb  = (const float*)d_in[i]; break;
            case BQ * JN * TN * 3:   sk   = (const float*)d_in[i]; break;
            case OUTN * KTOT:        W    = (const float*)d_in[i]; break;
            case OUTN:               bias = (const float*)d_in[i]; break;
            default: break;
        }
    }
    float* out = (float*)d_out;

    cudaFuncSetAttribute(main_kernel,
                         cudaFuncAttributeMaxDynamicSharedMemorySize, SMEM_MAIN);

    prep_kernel<<<(BQ * JN + 255) / 256, 256>>>(sk);
    bitmask_kernel<<<BQ, IMGC>>>();
    diff_kernel<<<IMGC, BQ>>>();
    main_kernel<<<dim3(XG, NO), 512, SMEM_MAIN>>>(W);
    final_kernel<<<BQ, OUTN>>>(rgb, bias, out);
}

// round 12
// speedup vs baseline: 1.2436x; 1.2436x over previous
#include <cuda_runtime.h>
#include <cstdint>

// ============================ problem constants ============================
constexpr int IMGC = 224;
constexpr int KTOT = IMGC * IMGC;     // 50176
constexpr int BQ   = 256;
constexpr int JN   = 25;
constexpr int TN   = 64;
constexpr int OUTN = 256;
constexpr int MIDJ = JN / 2;          // 12
constexpr int BOXC = 20;

constexpr int XG   = 37;              // x windows (grid.x)
constexpr int NO   = 8;               // n octants (grid.y), 32 n each
constexpr int NCOL = 32;
constexpr int EVS  = 32;              // int16 slots per (b,x): [count, ev...]

// smem floats: A[224][32] swz | stg[32][225] | T[16][33]
constexpr int F_A   = 0;
constexpr int F_STG = 224 * NCOL;                 // 7168
constexpr int F_T   = F_STG + NCOL * 225;         // 14368
constexpr int F_TOT = F_T + 16 * 33;              // 14896
constexpr uint32_t SMEM_MAIN = F_TOT * 4;         // 59584 B (2 CTAs/SM)

// ============================ scratch (device globals) =====================
__device__ __align__(256) unsigned long long g_bits[(size_t)IMGC * BQ * 4]; // 1.8MB
__device__ __align__(256) short g_ev[(size_t)IMGC * BQ * EVS];              // 3.7MB
__device__ __align__(256) float g_part[(size_t)XG * BQ * OUTN];             // 9.7MB
__device__ int g_px[BQ * JN];
__device__ int g_ylo[BQ * JN];
__device__ int g_yhi[BQ * JN];

// ============================ kernel 1: farthest-frame box params ==========
__global__ void prep_kernel(const float* __restrict__ sk) {
    int id = blockIdx.x * blockDim.x + threadIdx.x;
    if (id >= BQ * JN) return;
    int b = id / JN, j = id % JN;
    const float* base = sk + ((size_t)b * JN + j) * TN * 3;
    const float* midb = sk + ((size_t)b * JN + MIDJ) * TN * 3;

    float best = -1.0f;
    int   tb = 0;
    for (int t = 0; t < TN; t++) {
        float dx = base[t * 3 + 0] - midb[t * 3 + 0];
        float dy = base[t * 3 + 1] - midb[t * 3 + 1];
        float dz = base[t * 3 + 2] - midb[t * 3 + 2];
        float d2 = __fadd_rn(__fadd_rn(__fmul_rn(dx, dx), __fmul_rn(dy, dy)),
                             __fmul_rn(dz, dz));
        float d = __fsqrt_rn(d2);
        if (d > best) { best = d; tb = t; }   // first-max == argmax semantics
    }
    float x = base[tb * 3 + 0];
    float y = base[tb * 3 + 1];
    int px = (int)(__fmul_rn(x, 224.0f));     // truncation == astype(int32)
    int py = (int)(__fmul_rn(y, 224.0f));
    g_px[id]  = px;
    g_ylo[id] = (py < BOXC) ? 0 : py - BOXC;
    g_yhi[id] = (py > IMGC - BOXC) ? IMGC : py + BOXC;
}

// ============================ kernel 2: bitmask + diff events (fused) =======
__global__ void bitmask_diff_kernel() {
    const int b = blockIdx.x;
    const int x = threadIdx.x;

    __shared__ int spx[JN], slo[JN], shi[JN];
    __shared__ unsigned long long smm[IMGC][4];
    if (x < JN) {
        spx[x] = g_px[b * JN + x];
        slo[x] = g_ylo[b * JN + x];
        shi[x] = g_yhi[b * JN + x];
    }
    __syncthreads();

    unsigned long long m[4] = {0ull, 0ull, 0ull, 0ull};
#pragma unroll
    for (int j = 0; j < JN; j++) {
        if (j == MIDJ) continue;
        int px = spx[j];
        if (x >= px - BOXC && x < px + BOXC) {
            int lo = slo[j], hi = shi[j];
#pragma unroll
            for (int w = 0; w < 4; w++) {
                int l = lo - w * 64;  if (l < 0)  l = 0;
                int h = hi - w * 64;  if (h > 64) h = 64;
                if (l < h) {
                    unsigned long long hiM = (h == 64) ? ~0ull : ((1ull << h) - 1ull);
                    unsigned long long loM = (1ull << l) - 1ull;
                    m[w] |= hiM & ~loM;
                }
            }
        }
    }
    unsigned long long* dst = g_bits + ((size_t)x * BQ + b) * 4;
    dst[0] = m[0]; dst[1] = m[1]; dst[2] = m[2]; dst[3] = m[3];
    smm[x][0] = m[0]; smm[x][1] = m[1]; smm[x][2] = m[2]; smm[x][3] = m[3];
    __syncthreads();

    // diff events vs x+1 (x = 223 diffs against zeros; unused by main)
    unsigned long long mb0 = 0, mb1 = 0, mb2 = 0, mb3 = 0;
    if (x + 1 < IMGC) {
        mb0 = smm[x + 1][0]; mb1 = smm[x + 1][1];
        mb2 = smm[x + 1][2]; mb3 = smm[x + 1][3];
    }
    unsigned long long DA[4], DB[4];
    DA[0] = m[0] ^ ((m[0] >> 1) | (m[1] << 63));
    DA[1] = m[1] ^ ((m[1] >> 1) | (m[2] << 63));
    DA[2] = m[2] ^ ((m[2] >> 1) | (m[3] << 63));
    DA[3] = m[3] ^ (m[3] >> 1);
    DB[0] = mb0 ^ ((mb0 >> 1) | (mb1 << 63));
    DB[1] = mb1 ^ ((mb1 >> 1) | (mb2 << 63));
    DB[2] = mb2 ^ ((mb2 >> 1) | (mb3 << 63));
    DB[3] = mb3 ^ (mb3 >> 1);

    int sA = (m[0] & 1ull) ? 1 : -1;
    int sB = (mb0 & 1ull) ? 1 : -1;

    short* out = g_ev + ((size_t)x * BQ + b) * EVS;
    int cnt = 0;
#pragma unroll
    for (int wd = 0; wd < 4; wd++) {
        unsigned long long da = DA[wd], db = DB[wd];
        unsigned long long o = da | db;
        while (o) {
            int p = __ffsll((long long)o) - 1;
            o &= o - 1;
            int c = 0;
            if ((da >> p) & 1ull) { c += sA; sA = -sA; }
            if ((db >> p) & 1ull) { c -= sB; sB = -sB; }
            if (c != 0) {
                if (cnt < EVS - 1)
                    out[1 + cnt] = (short)(((wd * 64 + p) & 0xFF) | (c << 8));
                cnt++;
            }
        }
    }
    out[0] = (cnt > EVS - 1) ? (short)255 : (short)cnt;
}

// ============================ main kernel helpers ===========================
__device__ __forceinline__ void walk_mask(const unsigned long long* mp_,
                                          float mult, float4* acc,
                                          const float* sA_, int half) {
    const ulonglong2* mp = reinterpret_cast<const ulonglong2*>(mp_);
    ulonglong2 mA = __ldg(mp), mB = __ldg(mp + 1);
    unsigned long long d0 = mA.x ^ ((mA.x >> 1) | (mA.y << 63));
    unsigned long long d1 = mA.y ^ ((mA.y >> 1) | (mB.x << 63));
    unsigned long long d2 = mB.x ^ ((mB.x >> 1) | (mB.y << 63));
    unsigned long long d3 = mB.y ^ (mB.y >> 1);
    float sgn = (mA.x & 1ull) ? mult : -mult;

#pragma unroll
    for (int wd = 0; wd < 4; wd++) {
        unsigned long long d = (wd == 0) ? d0 : (wd == 1) ? d1
                             : (wd == 2) ? d2 : d3;
        while (d) {
            int p = __ffsll((long long)d) - 1;
            d &= d - 1;
            const int y = wd * 64 + p;
            const float4* row = reinterpret_cast<const float4*>(sA_) + y * 8;
#pragma unroll
            for (int r = 0; r < 4; r++) {
                float4 t = row[(half * 4 + r + y) & 7];
                acc[r].x = fmaf(sgn, t.x, acc[r].x);
                acc[r].y = fmaf(sgn, t.y, acc[r].y);
                acc[r].z = fmaf(sgn, t.z, acc[r].z);
                acc[r].w = fmaf(sgn, t.w, acc[r].w);
            }
            sgn = -sgn;
        }
    }
}

// ============================ kernel 3: serial scan + sparse gather =========
// grid (37, 8) = 296 CTAs = 2/SM. Per x:
//  stage: warp w copies W cols 2w,2w+1 into stg[n][225] (pitch 225 = CF)
//  ph1  : thread (col=t&31, seg=t>>5): serial sum of 14 y -> T[seg][col]
//  ph2  : warp 0: exclusive scan of 16 seg totals per column
//  ph3  : thread re-walks its segment, A[y][swz(n)] += running prefix
//         (warp = fixed seg, lane = col -> row-wise A write = 32 distinct
//          banks; zero SHFL anywhere, FADD chains on the idle FMA pipe)
//  gather: validated R11 diff-event walk vs accumulated A.
__global__ __launch_bounds__(512, 2)
void main_kernel(const float* __restrict__ W) {
    extern __shared__ float sm[];
    float* sA   = sm + F_A;
    float* stg  = sm + F_STG;
    float* sT   = sm + F_T;

    const int tid  = threadIdx.x;
    const int w    = tid >> 5;
    const int lane = tid & 31;
    const int xg   = blockIdx.x;
    const int n0   = blockIdx.y * NCOL;
    const int b    = tid >> 1;
    const int half = tid & 1;
    const int col  = tid & 31;            // ph1/ph3 column
    const int seg  = tid >> 5;            // ph1/ph3 segment (== w)

    const int x0 = (xg * IMGC) / XG;
    const int x1 = ((xg + 1) * IMGC) / XG;

    // zero A
#pragma unroll
    for (int r = 0; r < 14; r++) sA[tid + r * 512] = 0.f;

    float4 acc[4];
#pragma unroll
    for (int r = 0; r < 4; r++) acc[r] = make_float4(0.f, 0.f, 0.f, 0.f);
    __syncthreads();

    for (int x = x0; x < x1; x++) {
        // ---- stage: warp w -> cols 2w, 2w+1, coalesced LDG -> pitch-225 STS
        {
            float v[14];
#pragma unroll
            for (int c = 0; c < 2; c++) {
                const int n = w * 2 + c;
                const float* wp = W + (size_t)(n0 + n) * KTOT + x * IMGC + lane;
#pragma unroll
                for (int s = 0; s < 7; s++) v[c * 7 + s] = __ldg(wp + s * 32);
            }
#pragma unroll
            for (int c = 0; c < 2; c++) {
                const int n = w * 2 + c;
#pragma unroll
                for (int s = 0; s < 7; s++)
                    stg[n * 225 + s * 32 + lane] = v[c * 7 + s];
            }
        }
        __syncthreads();

        // ---- ph1: segment totals ----
        {
            const float* p = stg + col * 225 + seg * 14;
            float run = 0.f;
#pragma unroll
            for (int j = 0; j < 14; j++) run += p[j];
            sT[seg * 33 + col] = run;
        }
        __syncthreads();

        // ---- ph2: exclusive scan of 16 totals per column (warp 0) ----
        if (tid < 32) {
            float run = 0.f;
#pragma unroll
            for (int s = 0; s < 16; s++) {
                float t = sT[s * 33 + tid];
                sT[s * 33 + tid] = run;
                run += t;
            }
        }
        __syncthreads();

        // ---- ph3: A[y][swz] += prefix (row-wise, conflict-free) ----
        {
            float run = sT[seg * 33 + col];
            const float* p = stg + col * 225 + seg * 14;
            const int g4 = col >> 2;
            const int nc = col & 3;
#pragma unroll
            for (int j = 0; j < 14; j++) {
                const int y = seg * 14 + j;
                run += p[j];
                sA[y * 32 + (((g4 + y) & 7) << 2) + nc] += run;
            }
        }
        __syncthreads();

        // ---- gather ----
        if (x == x1 - 1) {
            walk_mask(g_bits + ((size_t)x * BQ + b) * 4, 1.f, acc, sA, half);
        } else {
            const short* ev = g_ev + ((size_t)x * BQ + b) * EVS;
            const int cnt = (int)__ldg(ev);
            if (cnt == 255) {
                walk_mask(g_bits + ((size_t)x * BQ + b) * 4,  1.f, acc, sA, half);
                walk_mask(g_bits + ((size_t)(x + 1) * BQ + b) * 4, -1.f, acc, sA, half);
            } else {
                for (int e = 0; e < cnt; e++) {
                    const int v = (int)__ldg(ev + 1 + e);
                    const int y = v & 0xFF;
                    const float fc = (float)(v >> 8);
                    const float4* row = reinterpret_cast<const float4*>(sA) + y * 8;
#pragma unroll
                    for (int r = 0; r < 4; r++) {
                        float4 t = row[(half * 4 + r + y) & 7];
                        acc[r].x = fmaf(fc, t.x, acc[r].x);
                        acc[r].y = fmaf(fc, t.y, acc[r].y);
                        acc[r].z = fmaf(fc, t.z, acc[r].z);
                        acc[r].w = fmaf(fc, t.w, acc[r].w);
                    }
                }
            }
        }
        __syncthreads();
    }

    // ---- write partials: acc[r] holds n = n0 + half*16 + 4r .. +3 ----
    float4* dst = reinterpret_cast<float4*>(
        g_part + ((size_t)xg * BQ + b) * OUTN + n0 + half * 16);
#pragma unroll
    for (int r = 0; r < 4; r++) dst[r] = acc[r];
}

// ============================ kernel 4: reduce + bias + rgb multiply ========
__global__ void final_kernel(const float* __restrict__ rgb,
                             const float* __restrict__ bias,
                             float* __restrict__ out) {
    const int b = blockIdx.x;
    const int o = threadIdx.x;
    float acc = 0.0f;
    const float* p = g_part + b * OUTN + o;
#pragma unroll
    for (int s = 0; s < XG; s++)
        acc += p[(size_t)s * (BQ * OUTN)];
    out[b * OUTN + o] = rgb[b * OUTN + o] * (acc + bias[o]);
}

// ============================ launch ========================================
extern "C" void kernel_launch(void* const* d_in, const int* in_sizes, int n_in,
                              void* d_out, int out_size) {
    const float* rgb = nullptr;
    const float* sk  = nullptr;
    const float* W   = nullptr;
    const float* bias = nullptr;
    for (int i = 0; i < n_in; i++) {
        switch (in_sizes[i]) {
            case BQ * OUTN:          rgb  = (const float*)d_in[i]; break;
            case BQ * JN * TN * 3:   sk   = (const float*)d_in[i]; break;
            case OUTN * KTOT:        W    = (const float*)d_in[i]; break;
            case OUTN:               bias = (const float*)d_in[i]; break;
            default: break;
        }
    }
    float* out = (float*)d_out;

    cudaFuncSetAttribute(main_kernel,
                         cudaFuncAttributeMaxDynamicSharedMemorySize, SMEM_MAIN);

    prep_kernel<<<(BQ * JN + 255) / 256, 256>>>(sk);
    bitmask_diff_kernel<<<BQ, IMGC>>>();
    main_kernel<<<dim3(XG, NO), 512, SMEM_MAIN>>>(W);
    final_kernel<<<BQ, OUTN>>>(rgb, bias, out);
}

// round 13
// speedup vs baseline: 1.4108x; 1.1344x over previous
#include <cuda_runtime.h>
#include <cstdint>

// ============================ problem constants ============================
constexpr int IMGC = 224;
constexpr int KTOT = IMGC * IMGC;     // 50176
constexpr int BQ   = 256;
constexpr int JN   = 25;
constexpr int TN   = 64;
constexpr int OUTN = 256;
constexpr int MIDJ = JN / 2;          // 12
constexpr int BOXC = 20;

constexpr int XG   = 37;              // x windows (grid.x)
constexpr int NO   = 8;               // n octants (grid.y), 32 n each
constexpr int NCOL = 32;
constexpr int EVS  = 32;              // int16 slots per (b,x): [count, ev...]

// smem floats: A[224][32] swz | stg[32][225] | T[16][33]
constexpr int F_A   = 0;
constexpr int F_STG = 224 * NCOL;                 // 7168
constexpr int F_T   = F_STG + NCOL * 225;         // 14368
constexpr int F_TOT = F_T + 16 * 33;              // 14896
constexpr uint32_t SMEM_MAIN = F_TOT * 4;         // 59584 B (2 CTAs/SM)

// ============================ scratch (device globals) =====================
__device__ __align__(256) unsigned long long g_bits[(size_t)IMGC * BQ * 4]; // 1.8MB
__device__ __align__(256) short g_ev[(size_t)IMGC * BQ * EVS];              // 3.7MB
__device__ __align__(256) float g_acc[(size_t)BQ * OUTN];                   // 256KB

// ============================ kernel 1: setup (prep+bitmask+diff+zero) =====
// grid = b (256), 224 threads. Threads 0..24: per-joint farthest-frame box;
// then all threads build the per-x y-bitmask, store g_bits, and emit the
// x->x+1 signed transition-diff events. Also zeroes g_acc[b].
__global__ void setup_kernel(const float* __restrict__ sk) {
    const int b = blockIdx.x;
    const int x = threadIdx.x;

    __shared__ int spx[JN], slo[JN], shi[JN];
    __shared__ unsigned long long smm[IMGC][4];

    // zero this batch's accumulator slice
    for (int i = x; i < OUTN; i += IMGC) g_acc[b * OUTN + i] = 0.f;

    if (x < JN) {
        const int j = x;
        const float* base = sk + ((size_t)b * JN + j) * TN * 3;
        const float* midb = sk + ((size_t)b * JN + MIDJ) * TN * 3;
        float best = -1.0f;
        int   tb = 0;
        for (int t = 0; t < TN; t++) {
            float dx = base[t * 3 + 0] - midb[t * 3 + 0];
            float dy = base[t * 3 + 1] - midb[t * 3 + 1];
            float dz = base[t * 3 + 2] - midb[t * 3 + 2];
            float d2 = __fadd_rn(__fadd_rn(__fmul_rn(dx, dx), __fmul_rn(dy, dy)),
                                 __fmul_rn(dz, dz));
            float d = __fsqrt_rn(d2);
            if (d > best) { best = d; tb = t; }   // first-max == argmax
        }
        float fx = base[tb * 3 + 0];
        float fy = base[tb * 3 + 1];
        int px = (int)(__fmul_rn(fx, 224.0f));    // truncation == astype(int32)
        int py = (int)(__fmul_rn(fy, 224.0f));
        spx[j] = px;
        slo[j] = (py < BOXC) ? 0 : py - BOXC;
        shi[j] = (py > IMGC - BOXC) ? IMGC : py + BOXC;
    }
    __syncthreads();

    unsigned long long m[4] = {0ull, 0ull, 0ull, 0ull};
#pragma unroll
    for (int j = 0; j < JN; j++) {
        if (j == MIDJ) continue;
        int px = spx[j];
        if (x >= px - BOXC && x < px + BOXC) {
            int lo = slo[j], hi = shi[j];
#pragma unroll
            for (int w = 0; w < 4; w++) {
                int l = lo - w * 64;  if (l < 0)  l = 0;
                int h = hi - w * 64;  if (h > 64) h = 64;
                if (l < h) {
                    unsigned long long hiM = (h == 64) ? ~0ull : ((1ull << h) - 1ull);
                    unsigned long long loM = (1ull << l) - 1ull;
                    m[w] |= hiM & ~loM;
                }
            }
        }
    }
    unsigned long long* dst = g_bits + ((size_t)x * BQ + b) * 4;
    dst[0] = m[0]; dst[1] = m[1]; dst[2] = m[2]; dst[3] = m[3];
    smm[x][0] = m[0]; smm[x][1] = m[1]; smm[x][2] = m[2]; smm[x][3] = m[3];
    __syncthreads();

    // diff events vs x+1
    unsigned long long mb0 = 0, mb1 = 0, mb2 = 0, mb3 = 0;
    if (x + 1 < IMGC) {
        mb0 = smm[x + 1][0]; mb1 = smm[x + 1][1];
        mb2 = smm[x + 1][2]; mb3 = smm[x + 1][3];
    }
    unsigned long long DA[4], DB[4];
    DA[0] = m[0] ^ ((m[0] >> 1) | (m[1] << 63));
    DA[1] = m[1] ^ ((m[1] >> 1) | (m[2] << 63));
    DA[2] = m[2] ^ ((m[2] >> 1) | (m[3] << 63));
    DA[3] = m[3] ^ (m[3] >> 1);
    DB[0] = mb0 ^ ((mb0 >> 1) | (mb1 << 63));
    DB[1] = mb1 ^ ((mb1 >> 1) | (mb2 << 63));
    DB[2] = mb2 ^ ((mb2 >> 1) | (mb3 << 63));
    DB[3] = mb3 ^ (mb3 >> 1);

    int sA = (m[0] & 1ull) ? 1 : -1;
    int sB = (mb0 & 1ull) ? 1 : -1;

    short* out = g_ev + ((size_t)x * BQ + b) * EVS;
    int cnt = 0;
#pragma unroll
    for (int wd = 0; wd < 4; wd++) {
        unsigned long long da = DA[wd], db = DB[wd];
        unsigned long long o = da | db;
        while (o) {
            int p = __ffsll((long long)o) - 1;
            o &= o - 1;
            int c = 0;
            if ((da >> p) & 1ull) { c += sA; sA = -sA; }
            if ((db >> p) & 1ull) { c -= sB; sB = -sB; }
            if (c != 0) {
                if (cnt < EVS - 1)
                    out[1 + cnt] = (short)(((wd * 64 + p) & 0xFF) | (c << 8));
                cnt++;
            }
        }
    }
    out[0] = (cnt > EVS - 1) ? (short)255 : (short)cnt;
}

// ============================ main kernel helpers ===========================
__device__ __forceinline__ void walk_mask(const unsigned long long* mp_,
                                          float mult, float4* acc,
                                          const float* sA_, int half) {
    const ulonglong2* mp = reinterpret_cast<const ulonglong2*>(mp_);
    ulonglong2 mA = __ldg(mp), mB = __ldg(mp + 1);
    unsigned long long d0 = mA.x ^ ((mA.x >> 1) | (mA.y << 63));
    unsigned long long d1 = mA.y ^ ((mA.y >> 1) | (mB.x << 63));
    unsigned long long d2 = mB.x ^ ((mB.x >> 1) | (mB.y << 63));
    unsigned long long d3 = mB.y ^ (mB.y >> 1);
    float sgn = (mA.x & 1ull) ? mult : -mult;

#pragma unroll
    for (int wd = 0; wd < 4; wd++) {
        unsigned long long d = (wd == 0) ? d0 : (wd == 1) ? d1
                             : (wd == 2) ? d2 : d3;
        while (d) {
            int p = __ffsll((long long)d) - 1;
            d &= d - 1;
            const int y = wd * 64 + p;
            const float4* row = reinterpret_cast<const float4*>(sA_) + y * 8;
#pragma unroll
            for (int r = 0; r < 4; r++) {
                float4 t = row[(half * 4 + r + y) & 7];
                acc[r].x = fmaf(sgn, t.x, acc[r].x);
                acc[r].y = fmaf(sgn, t.y, acc[r].y);
                acc[r].z = fmaf(sgn, t.z, acc[r].z);
                acc[r].w = fmaf(sgn, t.w, acc[r].w);
            }
            sgn = -sgn;
        }
    }
}

// ============================ kernel 2: serial scan + sparse gather =========
// grid (37, 8) = 296 CTAs = 2/SM. Per x (4 barriers):
//  stage: warp w copies W cols 2w,2w+1 into stg[n][225] (pitch 225 = CF)
//  ph1  : thread (col,seg): serial sum of its 14-y segment -> T[seg][col]
//  ph3  : thread sums T[0..seg-1][col] itself (warp-uniform trip count, CF
//         rows — replaces the old single-warp ph2 + a barrier), then
//         A[y][swz] += running prefix (row-wise write = 32 distinct banks)
//  gather: diff-event walk vs accumulated A (validated R11/R12 core)
//  epilogue: atomicAdd (REDG) into g_acc — no partials round-trip.
__global__ __launch_bounds__(512, 2)
void main_kernel(const float* __restrict__ W) {
    extern __shared__ float sm[];
    float* sA   = sm + F_A;
    float* stg  = sm + F_STG;
    float* sT   = sm + F_T;

    const int tid  = threadIdx.x;
    const int w    = tid >> 5;
    const int lane = tid & 31;
    const int xg   = blockIdx.x;
    const int n0   = blockIdx.y * NCOL;
    const int b    = tid >> 1;
    const int half = tid & 1;
    const int col  = tid & 31;            // ph1/ph3 column
    const int seg  = tid >> 5;            // ph1/ph3 segment (== w)

    const int x0 = (xg * IMGC) / XG;
    const int x1 = ((xg + 1) * IMGC) / XG;

    // zero A
#pragma unroll
    for (int r = 0; r < 14; r++) sA[tid + r * 512] = 0.f;

    float4 acc[4];
#pragma unroll
    for (int r = 0; r < 4; r++) acc[r] = make_float4(0.f, 0.f, 0.f, 0.f);
    __syncthreads();

    for (int x = x0; x < x1; x++) {
        // ---- stage: warp w -> cols 2w, 2w+1, coalesced LDG -> pitch-225 STS
        {
            float v[14];
#pragma unroll
            for (int c = 0; c < 2; c++) {
                const int n = w * 2 + c;
                const float* wp = W + (size_t)(n0 + n) * KTOT + x * IMGC + lane;
#pragma unroll
                for (int s = 0; s < 7; s++) v[c * 7 + s] = __ldg(wp + s * 32);
            }
#pragma unroll
            for (int c = 0; c < 2; c++) {
                const int n = w * 2 + c;
#pragma unroll
                for (int s = 0; s < 7; s++)
                    stg[n * 225 + s * 32 + lane] = v[c * 7 + s];
            }
        }
        __syncthreads();

        // ---- ph1: segment totals ----
        {
            const float* p = stg + col * 225 + seg * 14;
            float run = 0.f;
#pragma unroll
            for (int j = 0; j < 14; j++) run += p[j];
            sT[seg * 33 + col] = run;
        }
        __syncthreads();

        // ---- ph3: own-prefix of seg totals, then A[y][swz] += prefix ----
        {
            float run = 0.f;
            for (int s2 = 0; s2 < seg; s2++)   // warp-uniform trip count
                run += sT[s2 * 33 + col];
            const float* p = stg + col * 225 + seg * 14;
            const int g4 = col >> 2;
            const int nc = col & 3;
#pragma unroll
            for (int j = 0; j < 14; j++) {
                const int y = seg * 14 + j;
                run += p[j];
                sA[y * 32 + (((g4 + y) & 7) << 2) + nc] += run;
            }
        }
        __syncthreads();

        // ---- gather ----
        if (x == x1 - 1) {
            walk_mask(g_bits + ((size_t)x * BQ + b) * 4, 1.f, acc, sA, half);
        } else {
            const short* ev = g_ev + ((size_t)x * BQ + b) * EVS;
            const int cnt = (int)__ldg(ev);
            if (cnt == 255) {
                walk_mask(g_bits + ((size_t)x * BQ + b) * 4,  1.f, acc, sA, half);
                walk_mask(g_bits + ((size_t)(x + 1) * BQ + b) * 4, -1.f, acc, sA, half);
            } else {
                for (int e = 0; e < cnt; e++) {
                    const int v = (int)__ldg(ev + 1 + e);
                    const int y = v & 0xFF;
                    const float fc = (float)(v >> 8);
                    const float4* row = reinterpret_cast<const float4*>(sA) + y * 8;
#pragma unroll
                    for (int r = 0; r < 4; r++) {
                        float4 t = row[(half * 4 + r + y) & 7];
                        acc[r].x = fmaf(fc, t.x, acc[r].x);
                        acc[r].y = fmaf(fc, t.y, acc[r].y);
                        acc[r].z = fmaf(fc, t.z, acc[r].z);
                        acc[r].w = fmaf(fc, t.w, acc[r].w);
                    }
                }
            }
        }
        __syncthreads();
    }

    // ---- epilogue: REDG accumulate (no partials) ----
    float* dst = g_acc + (size_t)b * OUTN + n0 + half * 16;
#pragma unroll
    for (int r = 0; r < 4; r++) {
        atomicAdd(dst + 4 * r + 0, acc[r].x);
        atomicAdd(dst + 4 * r + 1, acc[r].y);
        atomicAdd(dst + 4 * r + 2, acc[r].z);
        atomicAdd(dst + 4 * r + 3, acc[r].w);
    }
}

// ============================ kernel 3: bias + rgb multiply =================
__global__ void final_kernel(const float* __restrict__ rgb,
                             const float* __restrict__ bias,
                             float* __restrict__ out) {
    const int idx = blockIdx.x * 256 + threadIdx.x;   // float4 index
    const int o4  = (idx & 63) * 4;
    float4 a  = *reinterpret_cast<const float4*>(g_acc + idx * 4);
    float4 bi = *reinterpret_cast<const float4*>(bias + o4);
    float4 rg = *reinterpret_cast<const float4*>(rgb + idx * 4);
    float4 res;
    res.x = rg.x * (a.x + bi.x);
    res.y = rg.y * (a.y + bi.y);
    res.z = rg.z * (a.z + bi.z);
    res.w = rg.w * (a.w + bi.w);
    *reinterpret_cast<float4*>(out + idx * 4) = res;
}

// ============================ launch ========================================
extern "C" void kernel_launch(void* const* d_in, const int* in_sizes, int n_in,
                              void* d_out, int out_size) {
    const float* rgb = nullptr;
    const float* sk  = nullptr;
    const float* W   = nullptr;
    const float* bias = nullptr;
    for (int i = 0; i < n_in; i++) {
        switch (in_sizes[i]) {
            case BQ * OUTN:          rgb  = (const float*)d_in[i]; break;
            case BQ * JN * TN * 3:   sk   = (const float*)d_in[i]; break;
            case OUTN * KTOT:        W    = (const float*)d_in[i]; break;
            case OUTN:               bias = (const float*)d_in[i]; break;
            default: break;
        }
    }
    float* out = (float*)d_out;

    cudaFuncSetAttribute(main_kernel,
                         cudaFuncAttributeMaxDynamicSharedMemorySize, SMEM_MAIN);

    setup_kernel<<<BQ, IMGC>>>(sk);
    main_kernel<<<dim3(XG, NO), 512, SMEM_MAIN>>>(W);
    final_kernel<<<BQ / 4, 256>>>(rgb, bias, out);
}

// round 14
// speedup vs baseline: 1.7814x; 1.2627x over previous
#include <cuda_runtime.h>
#include <cstdint>

// ============================ problem constants ============================
constexpr int IMGC = 224;
constexpr int KTOT = IMGC * IMGC;     // 50176
constexpr int BQ   = 256;
constexpr int JN   = 25;
constexpr int TN   = 64;
constexpr int OUTN = 256;
constexpr int MIDJ = JN / 2;          // 12
constexpr int BOXC = 20;

constexpr int XG   = 37;              // x windows (grid.x)
constexpr int NO   = 8;               // n octants (grid.y), 32 n each
constexpr int NCOL = 32;
constexpr int EVS  = 32;              // int16 slots per (b,x): [count, ev...]

// smem floats: A[224][32] swz | stg[32][225] | T[16][33]
constexpr int F_A   = 0;
constexpr int F_STG = 224 * NCOL;                 // 7168
constexpr int F_T   = F_STG + NCOL * 225;         // 14368
constexpr int F_TOT = F_T + 16 * 33;              // 14896
constexpr uint32_t SMEM_MAIN = F_TOT * 4;         // 59584 B (2 CTAs/SM)

// ============================ scratch (device globals) =====================
__device__ __align__(256) unsigned long long g_bits[(size_t)IMGC * BQ * 4]; // 1.8MB
__device__ __align__(256) short g_ev[(size_t)IMGC * BQ * EVS];              // 3.7MB
__device__ __align__(256) float g_acc[(size_t)BQ * OUTN];                   // 256KB

// ============================ kernel 1: setup (prep+bitmask+diff+zero) =====
// grid = b (256), 224 threads (7 warps).
// Argmax phase: warp w handles joints j = w, w+7, ... ; lane t-parallel
// distance eval (frames lane, lane+32) + shfl butterfly argmax with
// first-index tiebreak. Mid joint staged in smem (one read, not 25).
// Then all 224 threads build the per-x y-bitmask + diff events (validated).
__global__ void setup_kernel(const float* __restrict__ sk) {
    const int b = blockIdx.x;
    const int x = threadIdx.x;
    const int w    = x >> 5;
    const int lane = x & 31;

    __shared__ int spx[JN], slo[JN], shi[JN];
    __shared__ float smid[TN * 3];
    __shared__ unsigned long long smm[IMGC][4];

    // zero this batch's accumulator slice
    for (int i = x; i < OUTN; i += IMGC) g_acc[b * OUTN + i] = 0.f;

    // stage mid-joint trajectory (192 floats)
    if (x < TN * 3)
        smid[x] = sk[((size_t)b * JN + MIDJ) * TN * 3 + x];
    __syncthreads();

    // warp-parallel farthest-frame argmax
    for (int j = w; j < JN; j += 7) {
        const float* base = sk + ((size_t)b * JN + j) * TN * 3;

        float bd; int bt;
        {
            // frame t0 = lane
            float dx = base[lane * 3 + 0] - smid[lane * 3 + 0];
            float dy = base[lane * 3 + 1] - smid[lane * 3 + 1];
            float dz = base[lane * 3 + 2] - smid[lane * 3 + 2];
            float d20 = __fadd_rn(__fadd_rn(__fmul_rn(dx, dx), __fmul_rn(dy, dy)),
                                  __fmul_rn(dz, dz));
            float d0 = __fsqrt_rn(d20);
            // frame t1 = lane + 32
            const int t1 = lane + 32;
            float ex = base[t1 * 3 + 0] - smid[t1 * 3 + 0];
            float ey = base[t1 * 3 + 1] - smid[t1 * 3 + 1];
            float ez = base[t1 * 3 + 2] - smid[t1 * 3 + 2];
            float d21 = __fadd_rn(__fadd_rn(__fmul_rn(ex, ex), __fmul_rn(ey, ey)),
                                  __fmul_rn(ez, ez));
            float d1 = __fsqrt_rn(d21);
            // first-max: equal -> earlier frame (t0)
            if (d0 >= d1) { bd = d0; bt = lane; }
            else          { bd = d1; bt = t1; }
        }
#pragma unroll
        for (int off = 16; off > 0; off >>= 1) {
            float od = __shfl_down_sync(0xffffffffu, bd, off);
            int   ot = __shfl_down_sync(0xffffffffu, bt, off);
            if (od > bd || (od == bd && ot < bt)) { bd = od; bt = ot; }
        }
        if (lane == 0) {
            float fx = base[bt * 3 + 0];
            float fy = base[bt * 3 + 1];
            int px = (int)(__fmul_rn(fx, 224.0f));   // truncation == astype
            int py = (int)(__fmul_rn(fy, 224.0f));
            spx[j] = px;
            slo[j] = (py < BOXC) ? 0 : py - BOXC;
            shi[j] = (py > IMGC - BOXC) ? IMGC : py + BOXC;
        }
    }
    __syncthreads();

    unsigned long long m[4] = {0ull, 0ull, 0ull, 0ull};
#pragma unroll
    for (int j = 0; j < JN; j++) {
        if (j == MIDJ) continue;
        int px = spx[j];
        if (x >= px - BOXC && x < px + BOXC) {
            int lo = slo[j], hi = shi[j];
#pragma unroll
            for (int wd = 0; wd < 4; wd++) {
                int l = lo - wd * 64;  if (l < 0)  l = 0;
                int h = hi - wd * 64;  if (h > 64) h = 64;
                if (l < h) {
                    unsigned long long hiM = (h == 64) ? ~0ull : ((1ull << h) - 1ull);
                    unsigned long long loM = (1ull << l) - 1ull;
                    m[wd] |= hiM & ~loM;
                }
            }
        }
    }
    unsigned long long* dst = g_bits + ((size_t)x * BQ + b) * 4;
    dst[0] = m[0]; dst[1] = m[1]; dst[2] = m[2]; dst[3] = m[3];
    smm[x][0] = m[0]; smm[x][1] = m[1]; smm[x][2] = m[2]; smm[x][3] = m[3];
    __syncthreads();

    // diff events vs x+1
    unsigned long long mb0 = 0, mb1 = 0, mb2 = 0, mb3 = 0;
    if (x + 1 < IMGC) {
        mb0 = smm[x + 1][0]; mb1 = smm[x + 1][1];
        mb2 = smm[x + 1][2]; mb3 = smm[x + 1][3];
    }
    unsigned long long DA[4], DB[4];
    DA[0] = m[0] ^ ((m[0] >> 1) | (m[1] << 63));
    DA[1] = m[1] ^ ((m[1] >> 1) | (m[2] << 63));
    DA[2] = m[2] ^ ((m[2] >> 1) | (m[3] << 63));
    DA[3] = m[3] ^ (m[3] >> 1);
    DB[0] = mb0 ^ ((mb0 >> 1) | (mb1 << 63));
    DB[1] = mb1 ^ ((mb1 >> 1) | (mb2 << 63));
    DB[2] = mb2 ^ ((mb2 >> 1) | (mb3 << 63));
    DB[3] = mb3 ^ (mb3 >> 1);

    int sA = (m[0] & 1ull) ? 1 : -1;
    int sB = (mb0 & 1ull) ? 1 : -1;

    short* out = g_ev + ((size_t)x * BQ + b) * EVS;
    int cnt = 0;
#pragma unroll
    for (int wd = 0; wd < 4; wd++) {
        unsigned long long da = DA[wd], db = DB[wd];
        unsigned long long o = da | db;
        while (o) {
            int p = __ffsll((long long)o) - 1;
            o &= o - 1;
            int c = 0;
            if ((da >> p) & 1ull) { c += sA; sA = -sA; }
            if ((db >> p) & 1ull) { c -= sB; sB = -sB; }
            if (c != 0) {
                if (cnt < EVS - 1)
                    out[1 + cnt] = (short)(((wd * 64 + p) & 0xFF) | (c << 8));
                cnt++;
            }
        }
    }
    out[0] = (cnt > EVS - 1) ? (short)255 : (short)cnt;
}

// ============================ main kernel helpers ===========================
__device__ __forceinline__ void walk_mask(const unsigned long long* mp_,
                                          float mult, float4* acc,
                                          const float* sA_, int half) {
    const ulonglong2* mp = reinterpret_cast<const ulonglong2*>(mp_);
    ulonglong2 mA = __ldg(mp), mB = __ldg(mp + 1);
    unsigned long long d0 = mA.x ^ ((mA.x >> 1) | (mA.y << 63));
    unsigned long long d1 = mA.y ^ ((mA.y >> 1) | (mB.x << 63));
    unsigned long long d2 = mB.x ^ ((mB.x >> 1) | (mB.y << 63));
    unsigned long long d3 = mB.y ^ (mB.y >> 1);
    float sgn = (mA.x & 1ull) ? mult : -mult;

#pragma unroll
    for (int wd = 0; wd < 4; wd++) {
        unsigned long long d = (wd == 0) ? d0 : (wd == 1) ? d1
                             : (wd == 2) ? d2 : d3;
        while (d) {
            int p = __ffsll((long long)d) - 1;
            d &= d - 1;
            const int y = wd * 64 + p;
            const float4* row = reinterpret_cast<const float4*>(sA_) + y * 8;
#pragma unroll
            for (int r = 0; r < 4; r++) {
                float4 t = row[(half * 4 + r + y) & 7];
                acc[r].x = fmaf(sgn, t.x, acc[r].x);
                acc[r].y = fmaf(sgn, t.y, acc[r].y);
                acc[r].z = fmaf(sgn, t.z, acc[r].z);
                acc[r].w = fmaf(sgn, t.w, acc[r].w);
            }
            sgn = -sgn;
        }
    }
}

// ============================ kernel 2: serial scan + sparse gather =========
// (validated R13 core, unchanged)
__global__ __launch_bounds__(512, 2)
void main_kernel(const float* __restrict__ W) {
    extern __shared__ float sm[];
    float* sA   = sm + F_A;
    float* stg  = sm + F_STG;
    float* sT   = sm + F_T;

    const int tid  = threadIdx.x;
    const int w    = tid >> 5;
    const int lane = tid & 31;
    const int xg   = blockIdx.x;
    const int n0   = blockIdx.y * NCOL;
    const int b    = tid >> 1;
    const int half = tid & 1;
    const int col  = tid & 31;
    const int seg  = tid >> 5;

    const int x0 = (xg * IMGC) / XG;
    const int x1 = ((xg + 1) * IMGC) / XG;

#pragma unroll
    for (int r = 0; r < 14; r++) sA[tid + r * 512] = 0.f;

    float4 acc[4];
#pragma unroll
    for (int r = 0; r < 4; r++) acc[r] = make_float4(0.f, 0.f, 0.f, 0.f);
    __syncthreads();

    for (int x = x0; x < x1; x++) {
        // ---- stage: warp w -> cols 2w, 2w+1, coalesced LDG -> pitch-225 STS
        {
            float v[14];
#pragma unroll
            for (int c = 0; c < 2; c++) {
                const int n = w * 2 + c;
                const float* wp = W + (size_t)(n0 + n) * KTOT + x * IMGC + lane;
#pragma unroll
                for (int s = 0; s < 7; s++) v[c * 7 + s] = __ldg(wp + s * 32);
            }
#pragma unroll
            for (int c = 0; c < 2; c++) {
                const int n = w * 2 + c;
#pragma unroll
                for (int s = 0; s < 7; s++)
                    stg[n * 225 + s * 32 + lane] = v[c * 7 + s];
            }
        }
        __syncthreads();

        // ---- ph1: segment totals ----
        {
            const float* p = stg + col * 225 + seg * 14;
            float run = 0.f;
#pragma unroll
            for (int j = 0; j < 14; j++) run += p[j];
            sT[seg * 33 + col] = run;
        }
        __syncthreads();

        // ---- ph3: own-prefix of seg totals, then A[y][swz] += prefix ----
        {
            float run = 0.f;
            for (int s2 = 0; s2 < seg; s2++)
                run += sT[s2 * 33 + col];
            const float* p = stg + col * 225 + seg * 14;
            const int g4 = col >> 2;
            const int nc = col & 3;
#pragma unroll
            for (int j = 0; j < 14; j++) {
                const int y = seg * 14 + j;
                run += p[j];
                sA[y * 32 + (((g4 + y) & 7) << 2) + nc] += run;
            }
        }
        __syncthreads();

        // ---- gather ----
        if (x == x1 - 1) {
            walk_mask(g_bits + ((size_t)x * BQ + b) * 4, 1.f, acc, sA, half);
        } else {
            const short* ev = g_ev + ((size_t)x * BQ + b) * EVS;
            const int cnt = (int)__ldg(ev);
            if (cnt == 255) {
                walk_mask(g_bits + ((size_t)x * BQ + b) * 4,  1.f, acc, sA, half);
                walk_mask(g_bits + ((size_t)(x + 1) * BQ + b) * 4, -1.f, acc, sA, half);
            } else {
                for (int e = 0; e < cnt; e++) {
                    const int v = (int)__ldg(ev + 1 + e);
                    const int y = v & 0xFF;
                    const float fc = (float)(v >> 8);
                    const float4* row = reinterpret_cast<const float4*>(sA) + y * 8;
#pragma unroll
                    for (int r = 0; r < 4; r++) {
                        float4 t = row[(half * 4 + r + y) & 7];
                        acc[r].x = fmaf(fc, t.x, acc[r].x);
                        acc[r].y = fmaf(fc, t.y, acc[r].y);
                        acc[r].z = fmaf(fc, t.z, acc[r].z);
                        acc[r].w = fmaf(fc, t.w, acc[r].w);
                    }
                }
            }
        }
        __syncthreads();
    }

    // ---- epilogue: REDG accumulate ----
    float* dst = g_acc + (size_t)b * OUTN + n0 + half * 16;
#pragma unroll
    for (int r = 0; r < 4; r++) {
        atomicAdd(dst + 4 * r + 0, acc[r].x);
        atomicAdd(dst + 4 * r + 1, acc[r].y);
        atomicAdd(dst + 4 * r + 2, acc[r].z);
        atomicAdd(dst + 4 * r + 3, acc[r].w);
    }
}

// ============================ kernel 3: bias + rgb multiply =================
__global__ void final_kernel(const float* __restrict__ rgb,
                             const float* __restrict__ bias,
                             float* __restrict__ out) {
    const int idx = blockIdx.x * 256 + threadIdx.x;   // float4 index
    const int o4  = (idx & 63) * 4;
    float4 a  = *reinterpret_cast<const float4*>(g_acc + idx * 4);
    float4 bi = *reinterpret_cast<const float4*>(bias + o4);
    float4 rg = *reinterpret_cast<const float4*>(rgb + idx * 4);
    float4 res;
    res.x = rg.x * (a.x + bi.x);
    res.y = rg.y * (a.y + bi.y);
    res.z = rg.z * (a.z + bi.z);
    res.w = rg.w * (a.w + bi.w);
    *reinterpret_cast<float4*>(out + idx * 4) = res;
}

// ============================ launch ========================================
extern "C" void kernel_launch(void* const* d_in, const int* in_sizes, int n_in,
                              void* d_out, int out_size) {
    const float* rgb = nullptr;
    const float* sk  = nullptr;
    const float* W   = nullptr;
    const float* bias = nullptr;
    for (int i = 0; i < n_in; i++) {
        switch (in_sizes[i]) {
            case BQ * OUTN:          rgb  = (const float*)d_in[i]; break;
            case BQ * JN * TN * 3:   sk   = (const float*)d_in[i]; break;
            case OUTN * KTOT:        W    = (const float*)d_in[i]; break;
            case OUTN:               bias = (const float*)d_in[i]; break;
            default: break;
        }
    }
    float* out = (float*)d_out;

    cudaFuncSetAttribute(main_kernel,
                         cudaFuncAttributeMaxDynamicSharedMemorySize, SMEM_MAIN);

    setup_kernel<<<BQ, IMGC>>>(sk);
    main_kernel<<<dim3(XG, NO), 512, SMEM_MAIN>>>(W);
    final_kernel<<<BQ / 4, 256>>>(rgb, bias, out);
}